// round 1
// baseline (speedup 1.0000x reference)
#include <cuda_runtime.h>

#define BB   32
#define TT   128
#define KD   32
#define HH   4
#define DINP 160
#define HIDN 256

// Scratch (static device globals; no allocation).
__device__ float g_act[BB * TT * DINP];   // [x | state] activations, 4096 x 160
__device__ float g_h1[BB * TT * HIDN];    // hidden1, 4096 x 256

// ---------------------------------------------------------------------------
// Kernel 1: fused projections + masked attention.
// Grid: B*H = 128 blocks, 256 threads. Thread t -> (row i = t>>1, half = t&1).
// Each thread computes full q-row (redundant, cheap), half the k/v kk-range,
// then processes half the j-range with online softmax; halves merged via smem.
// ---------------------------------------------------------------------------
__global__ void __launch_bounds__(256, 1) attn_kernel(
    const float* __restrict__ state,
    const float* __restrict__ Wq,
    const float* __restrict__ Wk,
    const float* __restrict__ Wv)
{
    __shared__ float s_kv[2 * TT * KD];      // [0,4096): K rows, [4096,8192): V rows (32KB)
    __shared__ float s_w[3 * KD * 36];       // transposed weights [mat][kk][c], pitch 36 (13.5KB)
    __shared__ float s_md[TT * 2];           // (m, d) partials from half==1 (1KB)

    const int bh   = blockIdx.x;
    const int b    = bh >> 2;
    const int h    = bh & 3;
    const int t    = threadIdx.x;
    const int i    = t >> 1;
    const int half = t & 1;

    float* s_k = s_kv;
    float* s_v = s_kv + TT * KD;

    // ---- stage weight slices transposed: s_w[mat][kk*36 + c] = W[c][h*32+kk]
    {
        const float* Wm[3] = {Wq, Wk, Wv};
        #pragma unroll
        for (int m = 0; m < 3; m++) {
            const float* W = Wm[m];
            float* sw = s_w + m * KD * 36;
            for (int n = t; n < KD * KD; n += 256) {
                int c = n >> 5, kk = n & 31;
                sw[kk * 36 + c] = W[c * (KD * HH) + h * KD + kk];
            }
        }
    }

    // ---- load my state row into registers (float4)
    float sr[KD];
    {
        const float4* p = (const float4*)(state + ((size_t)b * TT + i) * KD);
        #pragma unroll
        for (int w = 0; w < 8; w++) {
            float4 v = p[w];
            sr[4*w+0] = v.x; sr[4*w+1] = v.y; sr[4*w+2] = v.z; sr[4*w+3] = v.w;
        }
    }
    __syncthreads();

    // ---- projections
    float qr[KD];
    #pragma unroll
    for (int kk = 0; kk < KD; kk++) {
        const float* row = s_w + kk * 36;           // Wq^T row
        float a0 = 0.f, a1 = 0.f;
        #pragma unroll
        for (int c = 0; c < KD; c += 8) {
            float4 x = *(const float4*)(row + c);
            float4 y = *(const float4*)(row + c + 4);
            a0 = fmaf(sr[c+0], x.x, a0); a1 = fmaf(sr[c+1], x.y, a1);
            a0 = fmaf(sr[c+2], x.z, a0); a1 = fmaf(sr[c+3], x.w, a1);
            a0 = fmaf(sr[c+4], y.x, a0); a1 = fmaf(sr[c+5], y.y, a1);
            a0 = fmaf(sr[c+6], y.z, a0); a1 = fmaf(sr[c+7], y.w, a1);
        }
        qr[kk] = a0 + a1;
    }
    #pragma unroll
    for (int kk2 = 0; kk2 < 16; kk2++) {
        int kk = half * 16 + kk2;
        const float* rowk = s_w + (KD + kk) * 36;       // Wk^T row
        const float* rowv = s_w + (2 * KD + kk) * 36;   // Wv^T row
        float k0 = 0.f, k1 = 0.f, v0 = 0.f, v1 = 0.f;
        #pragma unroll
        for (int c = 0; c < KD; c += 4) {
            float4 xk = *(const float4*)(rowk + c);
            float4 xv = *(const float4*)(rowv + c);
            k0 = fmaf(sr[c+0], xk.x, k0); k1 = fmaf(sr[c+1], xk.y, k1);
            k0 = fmaf(sr[c+2], xk.z, k0); k1 = fmaf(sr[c+3], xk.w, k1);
            v0 = fmaf(sr[c+0], xv.x, v0); v1 = fmaf(sr[c+1], xv.y, v1);
            v0 = fmaf(sr[c+2], xv.z, v0); v1 = fmaf(sr[c+3], xv.w, v1);
        }
        s_k[i * KD + kk] = k0 + k1;
        s_v[i * KD + kk] = v0 + v1;
    }
    __syncthreads();

    // ---- online softmax over my half of the j-range
    const float scale = 0.17677669529663687f;   // 1/sqrt(32)
    float m = -1e30f, dsum = 0.f;
    float acc[KD];
    #pragma unroll
    for (int dd = 0; dd < KD; dd++) acc[dd] = 0.f;

    const int j0base = half * 64;
    for (int jb = 0; jb < 64; jb += 4) {
        float s[4];
        #pragma unroll
        for (int u = 0; u < 4; u++) {
            int j = j0base + jb + u;
            const float* krow = s_k + j * KD;
            float a0 = 0.f, a1 = 0.f;
            #pragma unroll
            for (int c = 0; c < KD; c += 8) {
                float4 x = *(const float4*)(krow + c);
                float4 y = *(const float4*)(krow + c + 4);
                a0 = fmaf(qr[c+0], x.x, a0); a1 = fmaf(qr[c+1], x.y, a1);
                a0 = fmaf(qr[c+2], x.z, a0); a1 = fmaf(qr[c+3], x.w, a1);
                a0 = fmaf(qr[c+4], y.x, a0); a1 = fmaf(qr[c+5], y.y, a1);
                a0 = fmaf(qr[c+6], y.z, a0); a1 = fmaf(qr[c+7], y.w, a1);
            }
            s[u] = (j == i) ? -1e30f : (a0 + a1) * scale;
        }
        // branchless rescale (f==1 when max unchanged; exp(-1e30-x)==0 cleans init)
        float bm = fmaxf(fmaxf(s[0], s[1]), fmaxf(s[2], s[3]));
        float nm = fmaxf(m, bm);
        float f = __expf(m - nm);
        dsum *= f;
        #pragma unroll
        for (int dd = 0; dd < KD; dd++) acc[dd] *= f;
        m = nm;
        float e[4];
        #pragma unroll
        for (int u = 0; u < 4; u++) { e[u] = __expf(s[u] - nm); dsum += e[u]; }
        #pragma unroll
        for (int u = 0; u < 4; u++) {
            const float* vrow = s_v + (j0base + jb + u) * KD;
            float ev = e[u];
            #pragma unroll
            for (int dd = 0; dd < KD; dd += 4) {
                float4 vv = *(const float4*)(vrow + dd);
                acc[dd+0] = fmaf(ev, vv.x, acc[dd+0]);
                acc[dd+1] = fmaf(ev, vv.y, acc[dd+1]);
                acc[dd+2] = fmaf(ev, vv.z, acc[dd+2]);
                acc[dd+3] = fmaf(ev, vv.w, acc[dd+3]);
            }
        }
    }

    // ---- merge the two halves (reuse s_k region for half==1 accumulators)
    __syncthreads();
    if (half) {
        s_md[i * 2 + 0] = m;
        s_md[i * 2 + 1] = dsum;
        float* dst = s_k + i * KD;
        #pragma unroll
        for (int dd = 0; dd < KD; dd++) dst[dd] = acc[dd];
    }
    __syncthreads();
    if (!half) {
        float m1 = s_md[i * 2 + 0], d1 = s_md[i * 2 + 1];
        float M  = fmaxf(m, m1);
        float f0 = __expf(m - M), f1 = __expf(m1 - M);
        float inv = 1.f / (dsum * f0 + d1 * f1);
        const float* a1p  = s_k + i * KD;
        const float* vrow = s_v + i * KD;
        float* orow = g_act + ((size_t)b * TT + i) * DINP;
        #pragma unroll
        for (int dd = 0; dd < KD; dd++) {
            orow[h * KD + dd] = (acc[dd] * f0 + a1p[dd] * f1) * inv - vrow[dd];
        }
        // state copy: head-block h owns concat cols [128 + h*8, 128 + h*8 + 8)
        #pragma unroll
        for (int dd = 0; dd < 8; dd++)
            orow[4 * KD + h * 8 + dd] = sr[h * 8 + dd];
    }
}

// ---------------------------------------------------------------------------
// Kernel 2: h1 = relu(act @ W1 + b1).  (4096,160)@(160,256)
// Grid 128 blocks x 256 threads; thread tile 8 rows x 4 cols (32 FMA per
// 8 LDS + 1 LDG.128 -> FMA-pipe bound).
// ---------------------------------------------------------------------------
__global__ void __launch_bounds__(256, 1) mlp1_kernel(
    const float* __restrict__ W1, const float* __restrict__ b1)
{
    __shared__ float s_a[32 * DINP];          // 20KB, row-major tile
    const int rbase = blockIdx.x * 32;
    const int t  = threadIdx.x;
    const int tc = t & 63, tr = t >> 6;
    const int c0 = tc * 4, r0 = tr * 8;

    {   // stage 32x160 activation tile (contiguous -> float4 copy)
        const float4* src = (const float4*)(g_act + (size_t)rbase * DINP);
        float4* dst = (float4*)s_a;
        #pragma unroll
        for (int n = t; n < 32 * DINP / 4; n += 256) dst[n] = src[n];
    }
    __syncthreads();

    float4 bb = *(const float4*)(b1 + c0);
    float acc[8][4];
    #pragma unroll
    for (int r = 0; r < 8; r++) {
        acc[r][0] = bb.x; acc[r][1] = bb.y; acc[r][2] = bb.z; acc[r][3] = bb.w;
    }

    #pragma unroll 4
    for (int kk = 0; kk < DINP; kk++) {
        float4 w = *(const float4*)(W1 + (size_t)kk * HIDN + c0);
        #pragma unroll
        for (int r = 0; r < 8; r++) {
            float a = s_a[(r0 + r) * DINP + kk];    // broadcast LDS
            acc[r][0] = fmaf(a, w.x, acc[r][0]);
            acc[r][1] = fmaf(a, w.y, acc[r][1]);
            acc[r][2] = fmaf(a, w.z, acc[r][2]);
            acc[r][3] = fmaf(a, w.w, acc[r][3]);
        }
    }

    #pragma unroll
    for (int r = 0; r < 8; r++) {
        float4 o;
        o.x = fmaxf(acc[r][0], 0.f); o.y = fmaxf(acc[r][1], 0.f);
        o.z = fmaxf(acc[r][2], 0.f); o.w = fmaxf(acc[r][3], 0.f);
        *(float4*)(g_h1 + ((size_t)(rbase + r0 + r)) * HIDN + c0) = o;
    }
}

// ---------------------------------------------------------------------------
// Kernel 3: h2 = relu(h1 @ W2 + b2); out = h2 @ Wo + bo (fused reduction).
// ---------------------------------------------------------------------------
__global__ void __launch_bounds__(256, 1) mlp2_kernel(
    const float* __restrict__ W2, const float* __restrict__ b2,
    const float* __restrict__ Wo, const float* __restrict__ bo,
    float* __restrict__ out)
{
    __shared__ float s_h[32 * HIDN];          // 32KB
    __shared__ float s_red[32 * 2];
    const int rbase = blockIdx.x * 32;
    const int t  = threadIdx.x;
    const int tc = t & 63, tr = t >> 6;
    const int c0 = tc * 4, r0 = tr * 8;

    {   // stage 32x256 h1 tile
        const float4* src = (const float4*)(g_h1 + (size_t)rbase * HIDN);
        float4* dst = (float4*)s_h;
        #pragma unroll
        for (int n = t; n < 32 * HIDN / 4; n += 256) dst[n] = src[n];
    }
    __syncthreads();

    float4 bb = *(const float4*)(b2 + c0);
    float acc[8][4];
    #pragma unroll
    for (int r = 0; r < 8; r++) {
        acc[r][0] = bb.x; acc[r][1] = bb.y; acc[r][2] = bb.z; acc[r][3] = bb.w;
    }

    #pragma unroll 4
    for (int kk = 0; kk < HIDN; kk++) {
        float4 w = *(const float4*)(W2 + (size_t)kk * HIDN + c0);
        #pragma unroll
        for (int r = 0; r < 8; r++) {
            float a = s_h[(r0 + r) * HIDN + kk];    // broadcast LDS
            acc[r][0] = fmaf(a, w.x, acc[r][0]);
            acc[r][1] = fmaf(a, w.y, acc[r][1]);
            acc[r][2] = fmaf(a, w.z, acc[r][2]);
            acc[r][3] = fmaf(a, w.w, acc[r][3]);
        }
    }

    // out partials: relu then dot with Wo slice
    float4 wo = *(const float4*)(Wo + c0);
    float p[8];
    #pragma unroll
    for (int r = 0; r < 8; r++) {
        float s = 0.f;
        s = fmaf(fmaxf(acc[r][0], 0.f), wo.x, s);
        s = fmaf(fmaxf(acc[r][1], 0.f), wo.y, s);
        s = fmaf(fmaxf(acc[r][2], 0.f), wo.z, s);
        s = fmaf(fmaxf(acc[r][3], 0.f), wo.w, s);
        p[r] = s;
    }
    // reduce across the 64 column-threads (2 warps per row-group)
    #pragma unroll
    for (int off = 16; off; off >>= 1) {
        #pragma unroll
        for (int r = 0; r < 8; r++)
            p[r] += __shfl_down_sync(0xffffffffu, p[r], off);
    }
    const int warp = t >> 5, lane = t & 31;
    if (lane == 0) {
        #pragma unroll
        for (int r = 0; r < 8; r++)
            s_red[(r0 + r) * 2 + (warp & 1)] = p[r];
    }
    __syncthreads();
    if (t < 32)
        out[rbase + t] = s_red[t * 2] + s_red[t * 2 + 1] + bo[0];
}

// ---------------------------------------------------------------------------
extern "C" void kernel_launch(void* const* d_in, const int* in_sizes, int n_in,
                              void* d_out, int out_size)
{
    (void)in_sizes; (void)n_in; (void)out_size;
    const float* state = (const float*)d_in[0];
    const float* Wq    = (const float*)d_in[1];
    const float* Wk    = (const float*)d_in[2];
    const float* Wv    = (const float*)d_in[3];
    const float* W1    = (const float*)d_in[4];
    const float* b1    = (const float*)d_in[5];
    const float* W2    = (const float*)d_in[6];
    const float* b2    = (const float*)d_in[7];
    const float* Wo    = (const float*)d_in[8];
    const float* bo    = (const float*)d_in[9];
    float* out = (float*)d_out;

    attn_kernel<<<BB * HH, 256>>>(state, Wq, Wk, Wv);
    mlp1_kernel<<<(BB * TT) / 32, 256>>>(W1, b1);
    mlp2_kernel<<<(BB * TT) / 32, 256>>>(W2, b2, Wo, bo, out);
}

// round 2
// speedup vs baseline: 1.0366x; 1.0366x over previous
#include <cuda_runtime.h>

#define BB   32
#define TT   128
#define KD   32
#define HH   4
#define DINP 160
#define HIDN 256

// Scratch (static device globals; no allocation).
__device__ float g_qT[BB * HH * KD * TT];   // [b][h][kk][i]  2MB
__device__ float g_kT[BB * HH * KD * TT];   // [b][h][kk][j]
__device__ float g_vT[BB * HH * KD * TT];   // [b][h][d][j]
__device__ float g_act[BB * TT * DINP];     // [x | state]  4096 x 160
__device__ float g_h1[BB * TT * HIDN];      // hidden1     4096 x 256

typedef unsigned long long ull;

__device__ __forceinline__ ull ffma2(ull a, ull b, ull c) {
    ull d;
    asm("fma.rn.f32x2 %0, %1, %2, %3;" : "=l"(d) : "l"(a), "l"(b), "l"(c));
    return d;
}
__device__ __forceinline__ ull pack2(float x, float y) {
    ull r;
    asm("mov.b64 %0, {%1, %2};" : "=l"(r) : "f"(x), "f"(y));
    return r;
}
__device__ __forceinline__ float2 unpack2(ull v) {
    float x, y;
    asm("mov.b64 {%0, %1}, %2;" : "=f"(x), "=f"(y) : "l"(v));
    return make_float2(x, y);
}

// ---------------------------------------------------------------------------
// Kernel 0: projections with transposed output.
// grid 384: blockIdx = rb (128 row-blocks of 32) + mat*128.
// C[m][row] written as g_{q,k,v}T[b][h][kk][i].
// ---------------------------------------------------------------------------
__global__ void __launch_bounds__(256) proj_kernel(
    const float* __restrict__ state,
    const float* __restrict__ Wq,
    const float* __restrict__ Wk,
    const float* __restrict__ Wv)
{
    __shared__ float sT[KD][36];       // stateT tile [c][r]
    __shared__ float Ws[KD * 128];     // W rows [k][c]

    const int bx  = blockIdx.x;
    const int rb  = bx & 127;
    const int mat = bx >> 7;
    const float* W = (mat == 0) ? Wq : (mat == 1) ? Wk : Wv;
    float* dstBase = (mat == 0) ? g_qT : (mat == 1) ? g_kT : g_vT;
    const int row0 = rb * 32;
    const int t = threadIdx.x;

    {   // stage W (32x128)
        const float4* src = (const float4*)W;
        float4* dst = (float4*)Ws;
        #pragma unroll
        for (int n = t; n < KD * 128 / 4; n += 256) dst[n] = src[n];
    }
    {   // stage state tile transposed
        int r = t >> 3, c0 = (t & 7) * 4;
        float4 v = *(const float4*)(state + (size_t)(row0 + r) * KD + c0);
        sT[c0 + 0][r] = v.x; sT[c0 + 1][r] = v.y;
        sT[c0 + 2][r] = v.z; sT[c0 + 3][r] = v.w;
    }
    __syncthreads();

    const int rg = t >> 5, cg = t & 31;
    const int r0 = rg * 4, c0 = cg * 4;
    ull acc[4][2];
    #pragma unroll
    for (int r = 0; r < 4; r++) { acc[r][0] = 0ull; acc[r][1] = 0ull; }

    #pragma unroll 8
    for (int k = 0; k < KD; k++) {
        float4 a4 = *(const float4*)&sT[k][r0];
        ulonglong2 b2 = *(const ulonglong2*)(Ws + k * 128 + c0);
        ull ad;
        ad = pack2(a4.x, a4.x); acc[0][0] = ffma2(ad, b2.x, acc[0][0]); acc[0][1] = ffma2(ad, b2.y, acc[0][1]);
        ad = pack2(a4.y, a4.y); acc[1][0] = ffma2(ad, b2.x, acc[1][0]); acc[1][1] = ffma2(ad, b2.y, acc[1][1]);
        ad = pack2(a4.z, a4.z); acc[2][0] = ffma2(ad, b2.x, acc[2][0]); acc[2][1] = ffma2(ad, b2.y, acc[2][1]);
        ad = pack2(a4.w, a4.w); acc[3][0] = ffma2(ad, b2.x, acc[3][0]); acc[3][1] = ffma2(ad, b2.y, acc[3][1]);
    }

    // transposed store
    const int b  = row0 >> 7;
    const int i0 = (row0 & 127) + r0;
    float cs[4][4];
    #pragma unroll
    for (int r = 0; r < 4; r++) {
        float2 p0 = unpack2(acc[r][0]), p1 = unpack2(acc[r][1]);
        cs[r][0] = p0.x; cs[r][1] = p0.y; cs[r][2] = p1.x; cs[r][3] = p1.y;
    }
    #pragma unroll
    for (int cc = 0; cc < 4; cc++) {
        int c = c0 + cc;
        int h = c >> 5, kk = c & 31;
        float4 o = make_float4(cs[0][cc], cs[1][cc], cs[2][cc], cs[3][cc]);
        *(float4*)(dstBase + ((size_t)((b * HH + h) * KD + kk)) * TT + i0) = o;
    }
}

// ---------------------------------------------------------------------------
// Kernel 1: masked attention for 64 query rows of one (b,h).
// grid 256 = (b, h, ihalf). Scores transposed in smem P[j][i].
// ---------------------------------------------------------------------------
__global__ void __launch_bounds__(256, 2) attn_kernel(const float* __restrict__ state)
{
    __shared__ float P[TT * 64];       // [j][i]  32KB
    __shared__ float s_mx[4][64];
    __shared__ float s_sm[4][64];
    __shared__ float s_inv[64];

    const int bx = blockIdx.x;
    const int b = bx >> 3, h = (bx >> 1) & 3, ihalf = bx & 1;
    const int t = threadIdx.x;
    const int ig0 = ihalf * 64;
    const float* QT = g_qT + (size_t)((b * HH + h) * KD) * TT;
    const float* KT = g_kT + (size_t)((b * HH + h) * KD) * TT;
    const float* VT = g_vT + (size_t)((b * HH + h) * KD) * TT;

    // ---- GEMM1: S^T[j][i] = K[j]·Q[i]; tile 8i x 4j
    {
        const int ig = t >> 5, jg = t & 31;
        const int i0 = ig * 8, j0 = jg * 4;
        ull acc[4][4];
        #pragma unroll
        for (int c = 0; c < 4; c++)
            #pragma unroll
            for (int p = 0; p < 4; p++) acc[c][p] = 0ull;

        #pragma unroll 4
        for (int kk = 0; kk < KD; kk++) {
            const float* qrow = QT + kk * TT + ig0 + i0;
            ulonglong2 a01 = *(const ulonglong2*)qrow;
            ulonglong2 a23 = *(const ulonglong2*)(qrow + 4);
            float4 bj = *(const float4*)(KT + kk * TT + j0);
            ull bd;
            bd = pack2(bj.x, bj.x);
            acc[0][0] = ffma2(bd, a01.x, acc[0][0]); acc[0][1] = ffma2(bd, a01.y, acc[0][1]);
            acc[0][2] = ffma2(bd, a23.x, acc[0][2]); acc[0][3] = ffma2(bd, a23.y, acc[0][3]);
            bd = pack2(bj.y, bj.y);
            acc[1][0] = ffma2(bd, a01.x, acc[1][0]); acc[1][1] = ffma2(bd, a01.y, acc[1][1]);
            acc[1][2] = ffma2(bd, a23.x, acc[1][2]); acc[1][3] = ffma2(bd, a23.y, acc[1][3]);
            bd = pack2(bj.z, bj.z);
            acc[2][0] = ffma2(bd, a01.x, acc[2][0]); acc[2][1] = ffma2(bd, a01.y, acc[2][1]);
            acc[2][2] = ffma2(bd, a23.x, acc[2][2]); acc[2][3] = ffma2(bd, a23.y, acc[2][3]);
            bd = pack2(bj.w, bj.w);
            acc[3][0] = ffma2(bd, a01.x, acc[3][0]); acc[3][1] = ffma2(bd, a01.y, acc[3][1]);
            acc[3][2] = ffma2(bd, a23.x, acc[3][2]); acc[3][3] = ffma2(bd, a23.y, acc[3][3]);
        }

        #pragma unroll
        for (int c = 0; c < 4; c++) {
            int jglob = j0 + c;
            int rd = jglob - ig0 - i0;          // diag position within my 8 i's
            if (rd >= 0 && rd < 8) {
                int p = rd >> 1, hi = rd & 1;
                float2 v = unpack2(acc[c][p]);
                if (hi) v.y = -1e30f; else v.x = -1e30f;
                acc[c][p] = pack2(v.x, v.y);
            }
            ull* dst = (ull*)&P[jglob * 64 + i0];
            dst[0] = acc[c][0]; dst[1] = acc[c][1];
            dst[2] = acc[c][2]; dst[3] = acc[c][3];
        }
    }
    __syncthreads();

    // ---- softmax (over j) on P, in place
    {
        const float scale = 0.17677669529663687f;   // 1/sqrt(32)
        const int i = t & 63, q = t >> 6;
        float mx = -1e30f;
        #pragma unroll 8
        for (int jj = 0; jj < 32; jj++)
            mx = fmaxf(mx, P[(q * 32 + jj) * 64 + i]);
        s_mx[q][i] = mx;
        __syncthreads();
        float m = fmaxf(fmaxf(s_mx[0][i], s_mx[1][i]), fmaxf(s_mx[2][i], s_mx[3][i]));
        float sum = 0.f;
        #pragma unroll 8
        for (int jj = 0; jj < 32; jj++) {
            int idx = (q * 32 + jj) * 64 + i;
            float e = __expf((P[idx] - m) * scale);
            P[idx] = e;
            sum += e;
        }
        s_sm[q][i] = sum;
    }
    // state copy into concat tail (no smem dependency)
    {
        #pragma unroll
        for (int n2 = t; n2 < 512; n2 += 256) {
            int r = n2 >> 3, c = n2 & 7;
            size_t row = (size_t)b * TT + ig0 + r;
            g_act[row * DINP + 4 * KD + h * 8 + c] = state[row * KD + h * 8 + c];
        }
    }
    __syncthreads();
    if (t < 64)
        s_inv[t] = 1.f / (s_sm[0][t] + s_sm[1][t] + s_sm[2][t] + s_sm[3][t]);
    __syncthreads();

    // ---- GEMM2: O[i][d] = sum_j P[j][i] * V[j][d]; tile 4i x 2d
    {
        const int ig = t & 15, dg = t >> 4;
        const int i0 = ig * 4, d0 = dg * 2;
        ull o[2][2];
        o[0][0] = 0ull; o[0][1] = 0ull; o[1][0] = 0ull; o[1][1] = 0ull;
        const float* v0p = VT + (size_t)d0 * TT;
        const float* v1p = VT + (size_t)(d0 + 1) * TT;

        #pragma unroll 4
        for (int j = 0; j < TT; j++) {
            ulonglong2 a = *(const ulonglong2*)&P[j * 64 + i0];
            ull vd0 = pack2(v0p[j], v0p[j]);
            ull vd1 = pack2(v1p[j], v1p[j]);
            o[0][0] = ffma2(vd0, a.x, o[0][0]); o[0][1] = ffma2(vd0, a.y, o[0][1]);
            o[1][0] = ffma2(vd1, a.x, o[1][0]); o[1][1] = ffma2(vd1, a.y, o[1][1]);
        }

        #pragma unroll
        for (int p = 0; p < 2; p++) {
            float2 e0 = unpack2(o[0][p]);
            float2 e1 = unpack2(o[1][p]);
            float r0[2] = {e0.x, e0.y};
            float r1[2] = {e1.x, e1.y};
            #pragma unroll
            for (int u = 0; u < 2; u++) {
                int il = i0 + p * 2 + u;
                int iglob = ig0 + il;
                float inv = s_inv[il];
                float out0 = r0[u] * inv - v0p[iglob];
                float out1 = r1[u] * inv - v1p[iglob];
                *(float2*)(g_act + ((size_t)b * TT + iglob) * DINP + h * KD + d0)
                    = make_float2(out0, out1);
            }
        }
    }
}

// ---------------------------------------------------------------------------
// Kernel 2: h1 = relu(act @ W1 + b1).  16 rows/block, grid 256.
// Activations pre-duplicated in smem -> 1 LDS.64 per packed (a,a).
// ---------------------------------------------------------------------------
__global__ void __launch_bounds__(256) mlp1_kernel(
    const float* __restrict__ W1, const float* __restrict__ b1)
{
    __shared__ ull s_a2[16 * DINP];        // 20KB dup'd
    const int rbase = blockIdx.x * 16;
    const int t = threadIdx.x;

    {
        const float4* src = (const float4*)(g_act + (size_t)rbase * DINP);
        #pragma unroll
        for (int n = t; n < 16 * DINP / 4; n += 256) {
            float4 v = src[n];
            ull* d = &s_a2[n * 4];
            d[0] = pack2(v.x, v.x); d[1] = pack2(v.y, v.y);
            d[2] = pack2(v.z, v.z); d[3] = pack2(v.w, v.w);
        }
    }
    __syncthreads();

    const int cg = t & 63, rg = t >> 6;
    const int c0 = cg * 4, r0 = rg * 4;
    float4 bias = *(const float4*)(b1 + c0);
    ull bp0 = pack2(bias.x, bias.y), bp1 = pack2(bias.z, bias.w);
    ull acc[4][2];
    #pragma unroll
    for (int r = 0; r < 4; r++) { acc[r][0] = bp0; acc[r][1] = bp1; }

    #pragma unroll 4
    for (int kk = 0; kk < DINP; kk++) {
        ulonglong2 w = *(const ulonglong2*)(W1 + (size_t)kk * HIDN + c0);
        #pragma unroll
        for (int r = 0; r < 4; r++) {
            ull a = s_a2[(r0 + r) * DINP + kk];
            acc[r][0] = ffma2(a, w.x, acc[r][0]);
            acc[r][1] = ffma2(a, w.y, acc[r][1]);
        }
    }

    #pragma unroll
    for (int r = 0; r < 4; r++) {
        float2 p0 = unpack2(acc[r][0]), p1 = unpack2(acc[r][1]);
        float4 o = make_float4(fmaxf(p0.x, 0.f), fmaxf(p0.y, 0.f),
                               fmaxf(p1.x, 0.f), fmaxf(p1.y, 0.f));
        *(float4*)(g_h1 + ((size_t)(rbase + r0 + r)) * HIDN + c0) = o;
    }
}

// ---------------------------------------------------------------------------
// Kernel 3: h2 = relu(h1 @ W2 + b2); out = h2 @ Wo + bo (fused).
// ---------------------------------------------------------------------------
__global__ void __launch_bounds__(256) mlp2_kernel(
    const float* __restrict__ W2, const float* __restrict__ b2,
    const float* __restrict__ Wo, const float* __restrict__ bo,
    float* __restrict__ out)
{
    __shared__ ull s_h2[16 * HIDN];        // 32KB dup'd
    __shared__ float s_red[16][2];
    const int rbase = blockIdx.x * 16;
    const int t = threadIdx.x;

    {
        const float4* src = (const float4*)(g_h1 + (size_t)rbase * HIDN);
        #pragma unroll
        for (int n = t; n < 16 * HIDN / 4; n += 256) {
            float4 v = src[n];
            ull* d = &s_h2[n * 4];
            d[0] = pack2(v.x, v.x); d[1] = pack2(v.y, v.y);
            d[2] = pack2(v.z, v.z); d[3] = pack2(v.w, v.w);
        }
    }
    __syncthreads();

    const int cg = t & 63, rg = t >> 6;
    const int c0 = cg * 4, r0 = rg * 4;
    float4 bias = *(const float4*)(b2 + c0);
    ull bp0 = pack2(bias.x, bias.y), bp1 = pack2(bias.z, bias.w);
    ull acc[4][2];
    #pragma unroll
    for (int r = 0; r < 4; r++) { acc[r][0] = bp0; acc[r][1] = bp1; }

    #pragma unroll 4
    for (int kk = 0; kk < HIDN; kk++) {
        ulonglong2 w = *(const ulonglong2*)(W2 + (size_t)kk * HIDN + c0);
        #pragma unroll
        for (int r = 0; r < 4; r++) {
            ull a = s_h2[(r0 + r) * HIDN + kk];
            acc[r][0] = ffma2(a, w.x, acc[r][0]);
            acc[r][1] = ffma2(a, w.y, acc[r][1]);
        }
    }

    // relu then dot with Wo slice
    float4 wo = *(const float4*)(Wo + c0);
    float p[4];
    #pragma unroll
    for (int r = 0; r < 4; r++) {
        float2 p0 = unpack2(acc[r][0]), p1 = unpack2(acc[r][1]);
        float s = 0.f;
        s = fmaf(fmaxf(p0.x, 0.f), wo.x, s);
        s = fmaf(fmaxf(p0.y, 0.f), wo.y, s);
        s = fmaf(fmaxf(p1.x, 0.f), wo.z, s);
        s = fmaf(fmaxf(p1.y, 0.f), wo.w, s);
        p[r] = s;
    }
    #pragma unroll
    for (int off = 16; off; off >>= 1) {
        #pragma unroll
        for (int r = 0; r < 4; r++)
            p[r] += __shfl_down_sync(0xffffffffu, p[r], off);
    }
    const int warp = t >> 5, lane = t & 31;
    if (lane == 0) {
        #pragma unroll
        for (int r = 0; r < 4; r++)
            s_red[r0 + r][warp & 1] = p[r];
    }
    __syncthreads();
    if (t < 16)
        out[rbase + t] = s_red[t][0] + s_red[t][1] + bo[0];
}

// ---------------------------------------------------------------------------
extern "C" void kernel_launch(void* const* d_in, const int* in_sizes, int n_in,
                              void* d_out, int out_size)
{
    (void)in_sizes; (void)n_in; (void)out_size;
    const float* state = (const float*)d_in[0];
    const float* Wq    = (const float*)d_in[1];
    const float* Wk    = (const float*)d_in[2];
    const float* Wv    = (const float*)d_in[3];
    const float* W1    = (const float*)d_in[4];
    const float* b1    = (const float*)d_in[5];
    const float* W2    = (const float*)d_in[6];
    const float* b2    = (const float*)d_in[7];
    const float* Wo    = (const float*)d_in[8];
    const float* bo    = (const float*)d_in[9];
    float* out = (float*)d_out;

    proj_kernel<<<384, 256>>>(state, Wq, Wk, Wv);
    attn_kernel<<<BB * HH * 2, 256>>>(state);
    mlp1_kernel<<<(BB * TT) / 16, 256>>>(W1, b1);
    mlp2_kernel<<<(BB * TT) / 16, 256>>>(W2, b2, Wo, bo, out);
}